// round 2
// baseline (speedup 1.0000x reference)
#include <cuda_runtime.h>
#include <cuda_bf16.h>

// Problem constants (fixed by the dataset)
#define BB      4
#define CC      8
#define NVOX    1048576      // 64*128*128
#define K_RATIO 0.2f

// Histogram config: bucket = float_bits(ce) >> SHIFT  (ce >= 0 so monotonic)
#define SHIFT   15
#define NBUCK   49152
#define NWORDS  (NBUCK/2)      // packed u16 pairs
#define SMEM_BYTES (NWORDS*4)  // 98304 B dynamic shared

#define GRID1   74
#define THR1    512
#define BLK3    32
#define THR3    512

// ---- static device scratch (no allocations allowed) ----
__device__ unsigned int g_hist[BB][NBUCK];
__device__ float        g_scratch[(size_t)BB * NVOX];   // 16 MB
__device__ int          g_T[BB];
__device__ int          g_k[BB];
__device__ int          g_nvalid[BB];
__device__ long long    g_above[BB];
__device__ double       g_pa[BB][BLK3];
__device__ double       g_pb[BB][BLK3];

// ---------------------------------------------------------------------------
// Kernel 0: zero the global histogram (replayed every graph launch)
// ---------------------------------------------------------------------------
__global__ void k_zero() {
    int total = BB * NBUCK;
    for (int i = blockIdx.x * blockDim.x + threadIdx.x; i < total;
         i += gridDim.x * blockDim.x)
        ((unsigned int*)g_hist)[i] = 0u;
}

// ---------------------------------------------------------------------------
// Pass 1: compute CE per voxel, write CE scratch, build per-batch histogram
// ---------------------------------------------------------------------------
__device__ __forceinline__ float vox_ce(float a0, float a1, float a2, float a3,
                                        float a4, float a5, float a6, float a7,
                                        int t, unsigned int* sh) {
    float m = fmaxf(fmaxf(fmaxf(a0, a1), fmaxf(a2, a3)),
                    fmaxf(fmaxf(a4, a5), fmaxf(a6, a7)));
    float s = __expf(a0 - m) + __expf(a1 - m) + __expf(a2 - m) + __expf(a3 - m)
            + __expf(a4 - m) + __expf(a5 - m) + __expf(a6 - m) + __expf(a7 - m);
    float xt = a0;
    if (t == 1) xt = a1;
    if (t == 2) xt = a2;
    if (t == 3) xt = a3;
    if (t == 4) xt = a4;
    if (t == 5) xt = a5;
    if (t == 6) xt = a6;
    if (t == 7) xt = a7;
    float ce = fmaxf(m + __logf(s) - xt, 0.0f);
    if (t != 0) {
        unsigned int idx = __float_as_uint(ce) >> SHIFT;
        if (idx > (NBUCK - 1)) idx = NBUCK - 1;
        atomicAdd(&sh[idx >> 1], (idx & 1u) ? 0x10000u : 1u);
        return ce;
    }
    return -1.0f;
}

__global__ void __launch_bounds__(THR1, 2)
k_pass1(const float* __restrict__ logits, const int* __restrict__ target) {
    extern __shared__ unsigned int sh[];
    const int tid = threadIdx.x;
    for (int j = tid; j < NWORDS; j += THR1) sh[j] = 0u;
    __syncthreads();

    const int b = blockIdx.y;
    const float* Lp = logits + (size_t)b * CC * NVOX;
    const int* Tp = target + (size_t)b * NVOX;
    float* Sp = g_scratch + (size_t)b * NVOX;

    const int stride = GRID1 * THR1 * 4;
    for (int i0 = (blockIdx.x * THR1 + tid) * 4; i0 < NVOX; i0 += stride) {
        float4 x0 = *(const float4*)(Lp + 0 * NVOX + i0);
        float4 x1 = *(const float4*)(Lp + 1 * NVOX + i0);
        float4 x2 = *(const float4*)(Lp + 2 * NVOX + i0);
        float4 x3 = *(const float4*)(Lp + 3 * NVOX + i0);
        float4 x4 = *(const float4*)(Lp + 4 * NVOX + i0);
        float4 x5 = *(const float4*)(Lp + 5 * NVOX + i0);
        float4 x6 = *(const float4*)(Lp + 6 * NVOX + i0);
        float4 x7 = *(const float4*)(Lp + 7 * NVOX + i0);
        int4 t4 = *(const int4*)(Tp + i0);   // int32 targets: 4 voxels per load

        float4 outv;
        outv.x = vox_ce(x0.x, x1.x, x2.x, x3.x, x4.x, x5.x, x6.x, x7.x, t4.x, sh);
        outv.y = vox_ce(x0.y, x1.y, x2.y, x3.y, x4.y, x5.y, x6.y, x7.y, t4.y, sh);
        outv.z = vox_ce(x0.z, x1.z, x2.z, x3.z, x4.z, x5.z, x6.z, x7.z, t4.z, sh);
        outv.w = vox_ce(x0.w, x1.w, x2.w, x3.w, x4.w, x5.w, x6.w, x7.w, t4.w, sh);
        *(float4*)(Sp + i0) = outv;
    }

    __syncthreads();
    // flush shared histogram (skip empty buckets)
    for (int j = tid; j < NWORDS; j += THR1) {
        unsigned int w = sh[j];
        unsigned int lo = w & 0xFFFFu;
        unsigned int hi = w >> 16;
        if (lo) atomicAdd(&g_hist[b][2 * j], lo);
        if (hi) atomicAdd(&g_hist[b][2 * j + 1], hi);
    }
}

// ---------------------------------------------------------------------------
// Pass 2: per batch, find n_valid, k, boundary bucket T, count strictly above
// ---------------------------------------------------------------------------
#define CH (NBUCK / 1024)   // 48 buckets per thread

__global__ void k_pass2() {
    __shared__ unsigned int part[1024];
    __shared__ unsigned int warpsum[32];
    const int tid = threadIdx.x;

    for (int b = 0; b < BB; b++) {
        unsigned int s = 0;
        const int base = tid * CH;
#pragma unroll
        for (int j = 0; j < CH; j++) s += g_hist[b][base + j];
        part[tid] = s;
        __syncthreads();

        if (tid < 32) {
            unsigned int w = 0;
#pragma unroll
            for (int j = 0; j < 32; j++) w += part[tid * 32 + j];
            warpsum[tid] = w;
        }
        __syncthreads();

        if (tid == 0) {
            long long nv = 0;
            for (int j = 0; j < 32; j++) nv += warpsum[j];
            int n_valid = (int)nv;
            // replicate reference: trunc(f32(n_valid) * f32(0.2)), clamp [1, n_valid]
            int k = (int)((float)n_valid * K_RATIO);
            if (k < 1) k = 1;
            if (k > n_valid) k = n_valid;   // == 0 iff n_valid == 0
            g_k[b] = k;
            g_nvalid[b] = n_valid;

            if (k > 0) {
                long long cum = 0;
                int wsel = 0;
                for (int wi = 31; wi >= 0; wi--) {
                    if (cum + (long long)warpsum[wi] >= (long long)k) { wsel = wi; break; }
                    cum += warpsum[wi];
                }
                int psel = wsel * 32;
                for (int pi = wsel * 32 + 31; pi >= wsel * 32; pi--) {
                    if (cum + (long long)part[pi] >= (long long)k) { psel = pi; break; }
                    cum += part[pi];
                }
                int T = psel * CH;
                for (int j = psel * CH + CH - 1; j >= psel * CH; j--) {
                    unsigned int c = g_hist[b][j];
                    if (cum + (long long)c >= (long long)k) { T = j; break; }
                    cum += c;
                }
                g_T[b] = T;
                g_above[b] = cum;   // count strictly above bucket T
            } else {
                g_T[b] = 0;         // safe sentinel (nv==0 path ignores it)
                g_above[b] = 0;
            }
        }
        __syncthreads();
    }
}

// ---------------------------------------------------------------------------
// Pass 3: exact sums — values in buckets > T, and values in bucket T
// ---------------------------------------------------------------------------
__global__ void k_pass3() {
    const int b = blockIdx.y;
    const int T = g_T[b];
    const float* Sp = g_scratch + (size_t)b * NVOX;

    float sa = 0.0f, sb = 0.0f;
    const int stride = BLK3 * THR3 * 4;
    for (int i0 = (blockIdx.x * THR3 + threadIdx.x) * 4; i0 < NVOX; i0 += stride) {
        float4 v = *(const float4*)(Sp + i0);
#define ACC(F) { float f = (F); if (f >= 0.0f) { \
            int idx = (int)(__float_as_uint(f) >> SHIFT); \
            if (idx > T) sa += f; else if (idx == T) sb += f; } }
        ACC(v.x) ACC(v.y) ACC(v.z) ACC(v.w)
#undef ACC
    }

    // deterministic block reduction in double
    double da = sa, db = sb;
#pragma unroll
    for (int o = 16; o > 0; o >>= 1) {
        da += __shfl_down_sync(0xFFFFFFFFu, da, o);
        db += __shfl_down_sync(0xFFFFFFFFu, db, o);
    }
    __shared__ double ra[16], rb[16];
    const int wid = threadIdx.x >> 5, lane = threadIdx.x & 31;
    if (lane == 0) { ra[wid] = da; rb[wid] = db; }
    __syncthreads();
    if (wid == 0) {
        da = (lane < (THR3 / 32)) ? ra[lane] : 0.0;
        db = (lane < (THR3 / 32)) ? rb[lane] : 0.0;
#pragma unroll
        for (int o = 8; o > 0; o >>= 1) {
            da += __shfl_down_sync(0xFFFFFFFFu, da, o);
            db += __shfl_down_sync(0xFFFFFFFFu, db, o);
        }
        if (lane == 0) {
            g_pa[b][blockIdx.x] = da;
            g_pb[b][blockIdx.x] = db;
        }
    }
}

// ---------------------------------------------------------------------------
// Pass 4: combine — one warp per batch, then scalar mean
// ---------------------------------------------------------------------------
__global__ void k_pass4(float* __restrict__ out) {
    const int tid = threadIdx.x;
    const int w = tid >> 5, lane = tid & 31;
    __shared__ double per[BB];
    if (w < BB) {
        const int b = w;
        double da = (lane < BLK3) ? g_pa[b][lane] : 0.0;
        double db = (lane < BLK3) ? g_pb[b][lane] : 0.0;
#pragma unroll
        for (int o = 16; o > 0; o >>= 1) {
            da += __shfl_down_sync(0xFFFFFFFFu, da, o);
            db += __shfl_down_sync(0xFFFFFFFFu, db, o);
        }
        if (lane == 0) {
            const int nv = g_nvalid[b];
            const int k = g_k[b];
            double p;
            if (nv == 0) {
                p = 0.0;   // fallback: mean of all-zero CE
            } else {
                const int T = g_T[b];
                const long long above = g_above[b];
                const long long r = (long long)k - above;   // 1..cnt[T]
                const unsigned int cnt = g_hist[b][T];
                const double mean_bb = cnt ? (db / (double)cnt) : 0.0;
                const double top_sum = da + (double)r * mean_bb;
                p = top_sum / (double)k;
            }
            per[b] = p;
        }
    }
    __syncthreads();
    if (tid == 0) {
        double acc = 0.0;
        for (int b = 0; b < BB; b++) acc += per[b];
        out[0] = (float)(acc / (double)BB);
    }
}

// ---------------------------------------------------------------------------
// Launch
// ---------------------------------------------------------------------------
extern "C" void kernel_launch(void* const* d_in, const int* in_sizes, int n_in,
                              void* d_out, int out_size) {
    const float* logits = (const float*)d_in[0];
    const int* target = (const int*)d_in[1];
    float* out = (float*)d_out;

    cudaFuncSetAttribute(k_pass1, cudaFuncAttributeMaxDynamicSharedMemorySize,
                         SMEM_BYTES);

    k_zero<<<96, 512>>>();
    k_pass1<<<dim3(GRID1, BB), THR1, SMEM_BYTES>>>(logits, target);
    k_pass2<<<1, 1024>>>();
    k_pass3<<<dim3(BLK3, BB), THR3>>>();
    k_pass4<<<1, 128>>>(out);
}

// round 5
// speedup vs baseline: 1.9637x; 1.9637x over previous
#include <cuda_runtime.h>
#include <cuda_bf16.h>

// Problem constants (fixed by the dataset)
#define BB      4
#define CC      8
#define NVOX    1048576      // 64*128*128
#define K_RATIO 0.2f

// Linear histogram: idx = min((int)(ce * 256.f), NB-1), range [0, 16)
#define NB      4096
#define NW      (NB/2)       // packed u16 pairs -> 8 KB static shared
#define BSCALE  256.0f

#define GRID1B  296          // blocks per batch for pass1 (1184 total)
#define THR1    256
#define BLK3    74           // blocks per batch for pass3 (296 total)
#define THR3    512

// ---- static device scratch (no allocations allowed) ----
__device__ unsigned int g_hist[BB][NB];
__device__ float        g_scratch[(size_t)BB * NVOX];   // 16 MB
__device__ int          g_T[BB];
__device__ int          g_k[BB];
__device__ int          g_nvalid[BB];
__device__ long long    g_above[BB];
__device__ double       g_pa[BB][BLK3];
__device__ double       g_pb[BB][BLK3];

// ---------------------------------------------------------------------------
// Kernel 0: zero the global histogram (replayed every graph launch)
// ---------------------------------------------------------------------------
__global__ void k_zero() {
    int total = BB * NB;
    for (int i = blockIdx.x * blockDim.x + threadIdx.x; i < total;
         i += gridDim.x * blockDim.x)
        ((unsigned int*)g_hist)[i] = 0u;
}

// ---------------------------------------------------------------------------
// Pass 1: compute CE per voxel, write CE scratch, build per-batch histogram
// ---------------------------------------------------------------------------
__device__ __forceinline__ float vox_ce(float a0, float a1, float a2, float a3,
                                        float a4, float a5, float a6, float a7,
                                        int t, unsigned int* sh) {
    float m = fmaxf(fmaxf(fmaxf(a0, a1), fmaxf(a2, a3)),
                    fmaxf(fmaxf(a4, a5), fmaxf(a6, a7)));
    float s = __expf(a0 - m) + __expf(a1 - m) + __expf(a2 - m) + __expf(a3 - m)
            + __expf(a4 - m) + __expf(a5 - m) + __expf(a6 - m) + __expf(a7 - m);
    float xt = a0;
    if (t == 1) xt = a1;
    if (t == 2) xt = a2;
    if (t == 3) xt = a3;
    if (t == 4) xt = a4;
    if (t == 5) xt = a5;
    if (t == 6) xt = a6;
    if (t == 7) xt = a7;
    float ce = fmaxf(m + __logf(s) - xt, 0.0f);
    if (t != 0) {
        int idx = (int)(ce * BSCALE);
        if (idx > NB - 1) idx = NB - 1;
        atomicAdd(&sh[idx >> 1], (idx & 1) ? 0x10000u : 1u);
        return ce;
    }
    return -1.0f;
}

__global__ void __launch_bounds__(THR1, 4)
k_pass1(const float* __restrict__ logits, const int* __restrict__ target) {
    __shared__ unsigned int sh[NW];
    const int tid = threadIdx.x;
    for (int j = tid; j < NW; j += THR1) sh[j] = 0u;
    __syncthreads();

    const int b = blockIdx.y;
    const float* Lp = logits + (size_t)b * CC * NVOX;
    const int* Tp = target + (size_t)b * NVOX;
    float* Sp = g_scratch + (size_t)b * NVOX;

    const int stride = GRID1B * THR1 * 4;
    for (int i0 = (blockIdx.x * THR1 + tid) * 4; i0 < NVOX; i0 += stride) {
        float4 x0 = *(const float4*)(Lp + 0 * NVOX + i0);
        float4 x1 = *(const float4*)(Lp + 1 * NVOX + i0);
        float4 x2 = *(const float4*)(Lp + 2 * NVOX + i0);
        float4 x3 = *(const float4*)(Lp + 3 * NVOX + i0);
        float4 x4 = *(const float4*)(Lp + 4 * NVOX + i0);
        float4 x5 = *(const float4*)(Lp + 5 * NVOX + i0);
        float4 x6 = *(const float4*)(Lp + 6 * NVOX + i0);
        float4 x7 = *(const float4*)(Lp + 7 * NVOX + i0);
        int4 t4 = *(const int4*)(Tp + i0);   // int32 targets: 4 voxels per load

        float4 outv;
        outv.x = vox_ce(x0.x, x1.x, x2.x, x3.x, x4.x, x5.x, x6.x, x7.x, t4.x, sh);
        outv.y = vox_ce(x0.y, x1.y, x2.y, x3.y, x4.y, x5.y, x6.y, x7.y, t4.y, sh);
        outv.z = vox_ce(x0.z, x1.z, x2.z, x3.z, x4.z, x5.z, x6.z, x7.z, t4.z, sh);
        outv.w = vox_ce(x0.w, x1.w, x2.w, x3.w, x4.w, x5.w, x6.w, x7.w, t4.w, sh);
        *(float4*)(Sp + i0) = outv;
    }

    __syncthreads();
    // flush shared histogram (skip empty buckets)
    for (int j = tid; j < NW; j += THR1) {
        unsigned int w = sh[j];
        unsigned int lo = w & 0xFFFFu;
        unsigned int hi = w >> 16;
        if (lo) atomicAdd(&g_hist[b][2 * j], lo);
        if (hi) atomicAdd(&g_hist[b][2 * j + 1], hi);
    }
}

// ---------------------------------------------------------------------------
// Pass 2: per batch, find n_valid, k, boundary bucket T, count strictly above
// ---------------------------------------------------------------------------
#define CH (NB / 1024)   // 4 buckets per thread

__global__ void k_pass2() {
    __shared__ unsigned int part[1024];
    __shared__ unsigned int warpsum[32];
    const int tid = threadIdx.x;

    for (int b = 0; b < BB; b++) {
        unsigned int s = 0;
        const int base = tid * CH;
#pragma unroll
        for (int j = 0; j < CH; j++) s += g_hist[b][base + j];
        part[tid] = s;
        __syncthreads();

        if (tid < 32) {
            unsigned int w = 0;
#pragma unroll
            for (int j = 0; j < 32; j++) w += part[tid * 32 + j];
            warpsum[tid] = w;
        }
        __syncthreads();

        if (tid == 0) {
            long long nv = 0;
            for (int j = 0; j < 32; j++) nv += warpsum[j];
            int n_valid = (int)nv;
            // replicate reference: trunc(f32(n_valid) * f32(0.2)), clamp [1, n_valid]
            int k = (int)((float)n_valid * K_RATIO);
            if (k < 1) k = 1;
            if (k > n_valid) k = n_valid;   // == 0 iff n_valid == 0
            g_k[b] = k;
            g_nvalid[b] = n_valid;

            if (k > 0) {
                long long cum = 0;
                int wsel = 0;
                for (int wi = 31; wi >= 0; wi--) {
                    if (cum + (long long)warpsum[wi] >= (long long)k) { wsel = wi; break; }
                    cum += warpsum[wi];
                }
                int psel = wsel * 32;
                for (int pi = wsel * 32 + 31; pi >= wsel * 32; pi--) {
                    if (cum + (long long)part[pi] >= (long long)k) { psel = pi; break; }
                    cum += part[pi];
                }
                int T = psel * CH;
                for (int j = psel * CH + CH - 1; j >= psel * CH; j--) {
                    unsigned int c = g_hist[b][j];
                    if (cum + (long long)c >= (long long)k) { T = j; break; }
                    cum += c;
                }
                g_T[b] = T;
                g_above[b] = cum;   // count strictly above bucket T
            } else {
                g_T[b] = 0;         // sentinel; nv==0 path ignores it
                g_above[b] = 0;
            }
        }
        __syncthreads();
    }
}

// ---------------------------------------------------------------------------
// Pass 3: exact sums — values in buckets > T, and values in bucket T
// ---------------------------------------------------------------------------
__global__ void __launch_bounds__(THR3)
k_pass3() {
    const int b = blockIdx.y;
    const int T = g_T[b];
    const float* Sp = g_scratch + (size_t)b * NVOX;

    float sa = 0.0f, sb = 0.0f;
    const int stride = BLK3 * THR3 * 4;
    for (int i0 = (blockIdx.x * THR3 + threadIdx.x) * 4; i0 < NVOX; i0 += stride) {
        float4 v = *(const float4*)(Sp + i0);
#define ACC(F) { float f = (F); if (f >= 0.0f) { \
            int idx = (int)(f * BSCALE); if (idx > NB - 1) idx = NB - 1; \
            if (idx > T) sa += f; else if (idx == T) sb += f; } }
        ACC(v.x) ACC(v.y) ACC(v.z) ACC(v.w)
#undef ACC
    }

    // deterministic block reduction in double
    double da = sa, db = sb;
#pragma unroll
    for (int o = 16; o > 0; o >>= 1) {
        da += __shfl_down_sync(0xFFFFFFFFu, da, o);
        db += __shfl_down_sync(0xFFFFFFFFu, db, o);
    }
    __shared__ double ra[16], rb[16];
    const int wid = threadIdx.x >> 5, lane = threadIdx.x & 31;
    if (lane == 0) { ra[wid] = da; rb[wid] = db; }
    __syncthreads();
    if (wid == 0) {
        da = (lane < (THR3 / 32)) ? ra[lane] : 0.0;
        db = (lane < (THR3 / 32)) ? rb[lane] : 0.0;
#pragma unroll
        for (int o = 8; o > 0; o >>= 1) {
            da += __shfl_down_sync(0xFFFFFFFFu, da, o);
            db += __shfl_down_sync(0xFFFFFFFFu, db, o);
        }
        if (lane == 0) {
            g_pa[b][blockIdx.x] = da;
            g_pb[b][blockIdx.x] = db;
        }
    }
}

// ---------------------------------------------------------------------------
// Pass 4: combine — one warp per batch (74 partials each), then scalar mean
// ---------------------------------------------------------------------------
__global__ void k_pass4(float* __restrict__ out) {
    const int tid = threadIdx.x;
    const int w = tid >> 5, lane = tid & 31;
    __shared__ double per[BB];
    if (w < BB) {
        const int b = w;
        double da = 0.0, db = 0.0;
        for (int i = lane; i < BLK3; i += 32) {
            da += g_pa[b][i];
            db += g_pb[b][i];
        }
#pragma unroll
        for (int o = 16; o > 0; o >>= 1) {
            da += __shfl_down_sync(0xFFFFFFFFu, da, o);
            db += __shfl_down_sync(0xFFFFFFFFu, db, o);
        }
        if (lane == 0) {
            const int nv = g_nvalid[b];
            const int k = g_k[b];
            double p;
            if (nv == 0) {
                p = 0.0;   // fallback: mean of all-zero CE
            } else {
                const int T = g_T[b];
                const long long above = g_above[b];
                const long long r = (long long)k - above;   // 1..cnt[T]
                const unsigned int cnt = g_hist[b][T];
                const double mean_bb = cnt ? (db / (double)cnt) : 0.0;
                const double top_sum = da + (double)r * mean_bb;
                p = top_sum / (double)k;
            }
            per[b] = p;
        }
    }
    __syncthreads();
    if (tid == 0) {
        double acc = 0.0;
        for (int b = 0; b < BB; b++) acc += per[b];
        out[0] = (float)(acc / (double)BB);
    }
}

// ---------------------------------------------------------------------------
// Launch
// ---------------------------------------------------------------------------
extern "C" void kernel_launch(void* const* d_in, const int* in_sizes, int n_in,
                              void* d_out, int out_size) {
    const float* logits = (const float*)d_in[0];
    const int* target = (const int*)d_in[1];
    float* out = (float*)d_out;

    k_zero<<<16, 512>>>();
    k_pass1<<<dim3(GRID1B, BB), THR1>>>(logits, target);
    k_pass2<<<1, 1024>>>();
    k_pass3<<<dim3(BLK3, BB), THR3>>>();
    k_pass4<<<1, 128>>>(out);
}